// round 15
// baseline (speedup 1.0000x reference)
#include <cuda_runtime.h>
#include <math.h>

#define HD    4096
#define NBLK  148
#define NTHR  1024
#define NWARP (NTHR / 32)
#define MAXS  16

// Persistent-kernel state (allocation-free scratch).
__device__ float g_h[2][HD];             // double-buffered hidden state
__device__ float g_part[MAXS][NBLK];     // per-step per-block halt partial sums
__device__ unsigned g_barcnt;            // grid barrier arrival count
__device__ volatile unsigned g_bargen;   // grid barrier generation

__device__ __forceinline__ void grid_barrier() {
    __syncthreads();
    if (threadIdx.x == 0) {
        __threadfence();                       // release
        unsigned gen = g_bargen;
        if (atomicAdd(&g_barcnt, 1u) == NBLK - 1u) {
            g_barcnt = 0u;
            __threadfence();
            g_bargen = gen + 1u;
        } else {
            while (g_bargen == gen) { }        // bare poll: fastest wake
        }
        __threadfence();                       // acquire
    }
    __syncthreads();
}

__device__ __forceinline__ float warp_red(float v) {
#pragma unroll
    for (int o = 16; o; o >>= 1) v += __shfl_xor_sync(0xffffffffu, v, o);
    return v;   // full sum on all lanes
}

__device__ __forceinline__ void pf_l2(const void* p) {
    asm volatile("prefetch.global.L2 [%0];" :: "l"(p));
}

// Replicated halt sum: every warp reads all NBLK partials (L2 broadcast) and
// reduces in identical order -> bit-identical result in every thread, no
// shared-memory broadcast or extra __syncthreads needed.
__device__ __forceinline__ float halt_sum(const float* part, int lane) {
    float a = 0.f;
#pragma unroll
    for (int i = lane; i < NBLK; i += 32) a += __ldcg(&part[i]);
    return warp_red(a);
}

__global__ void __launch_bounds__(NTHR, 1) arnn_kernel(
    const float* __restrict__ x,     const float* __restrict__ s,
    const float* __restrict__ W_ih,  const float* __restrict__ b_ih,
    const float* __restrict__ W_hh,  const float* __restrict__ b_hh,
    const float* __restrict__ w_halt,const float* __restrict__ b_halt,
    const float* __restrict__ W_out, const float* __restrict__ b_out,
    float* __restrict__ out)
{
    __shared__ float sx[HD];          // staged x (16 KB)
    __shared__ float sv[HD];          // staged h / s  (16 KB)
    __shared__ float red[NWARP];      // per-warp halt contributions

    const int tid  = threadIdx.x;
    const int lane = tid & 31;
    const int warp = tid >> 5;
    const int b    = blockIdx.x;

    // Balanced contiguous row ranges: every block gets 27-28 rows.
    const int r0    = (HD * b) / NBLK;
    const int r1    = (HD * (b + 1)) / NBLK;
    const int nrows = r1 - r0;
    const bool has_row = (warp < nrows);
    const int r     = r0 + warp;

    // ---- Stage x and s once (vectorized) ----
    {
        const float4* x4 = (const float4*)x;
        const float4* s4 = (const float4*)s;
        float4* sx4 = (float4*)sx;
        float4* sv4 = (float4*)sv;
        for (int i = tid; i < HD / 4; i += NTHR) { sx4[i] = x4[i]; sv4[i] = s4[i]; }
    }
    __syncthreads();

    const float bhalt = b_halt[0];
    float z_reg = 0.f, whalt_reg = 0.f;

    // ---- Fused phase-0 + step-0, dual-stream interleaved:
    //      z  = W_ih[:,1:] @ x + b_ih + b_hh   (evict-first stream)
    //      a0 = W_hh @ s                        (default: stays in L2 for step 1)
    //      h0 = tanh(z + W_ih[:,0] + a0)
    if (has_row) {
        const float* rowp = W_ih + (size_t)r * (HD + 1) + 1;   // misaligned by (r+1)&3
        const int mis  = (int)(((size_t)rowp >> 2) & 3);
        const int lead = (4 - mis) & 3;
        const float4* vA   = (const float4*)(rowp + lead);
        const float4* rowB = (const float4*)(W_hh + (size_t)r * HD);
        const float4* sv4  = (const float4*)sv;
        const int nA = (HD - lead) >> 2;                        // 1023 or 1024

        float accA = 0.f, accB = 0.f;
        if (lane < lead) accA = fmaf(__ldcs(rowp + lane), sx[lane], accA);

        // Branch-free main body: 992 vectors of each stream (31 iters/lane).
#pragma unroll 4
        for (int i = lane; i < 992; i += 32) {
            float4 wb = rowB[i];
            float4 h4 = sv4[i];
            accB = fmaf(wb.x, h4.x, accB);
            accB = fmaf(wb.y, h4.y, accB);
            accB = fmaf(wb.z, h4.z, accB);
            accB = fmaf(wb.w, h4.w, accB);
            float4 wa = __ldcs(vA + i);
            const int j = lead + 4 * i;
            accA = fmaf(wa.x, sx[j + 0], accA);
            accA = fmaf(wa.y, sx[j + 1], accA);
            accA = fmaf(wa.z, sx[j + 2], accA);
            accA = fmaf(wa.w, sx[j + 3], accA);
        }
        // Tail: B has 1024 vectors, A has 1023 (lead>0) or 1024 (lead==0).
        {
            const int i = 992 + lane;   // 992..1023
            float4 wb = rowB[i];
            float4 h4 = sv4[i];
            accB = fmaf(wb.x, h4.x, accB);
            accB = fmaf(wb.y, h4.y, accB);
            accB = fmaf(wb.z, h4.z, accB);
            accB = fmaf(wb.w, h4.w, accB);
            if (i < nA) {
                float4 wa = __ldcs(vA + i);
                const int j = lead + 4 * i;
                accA = fmaf(wa.x, sx[j + 0], accA);
                accA = fmaf(wa.y, sx[j + 1], accA);
                accA = fmaf(wa.z, sx[j + 2], accA);
                accA = fmaf(wa.w, sx[j + 3], accA);
            }
        }
        const int ts = lead + 4 * nA;
        if (lane < HD - ts) accA = fmaf(__ldcs(rowp + ts + lane), sx[ts + lane], accA);

        accA = warp_red(accA);
        accB = warp_red(accB);
        z_reg     = accA + b_ih[r] + b_hh[r];
        whalt_reg = w_halt[r];
        if (lane == 0) {
            float hn = tanhf(z_reg + __ldcs(rowp - 1) + accB);
            __stcg(&g_h[0][r], hn);
            red[warp] = whalt_reg * hn;
        }
    } else if (lane == 0) {
        red[warp] = 0.f;
    }
    __syncthreads();
    if (tid == 0) {                     // fixed-order per-block partial
        float p = 0.f;
        for (int w = 0; w < nrows; w++) p += red[w];
        __stcg(&g_part[0][b], p);
    }
    grid_barrier();

    float cum = 0.f;
    int   t   = 0;

    for (;;) {
        // ---- Deterministic replicated halt decision (every warp, no sync) ----
        {
            float hsum = halt_sum(g_part[t], lane);
            float p = 1.f / (1.f + expf(-(hsum + bhalt)));
            cum += p;
            if (cum >= 0.99f || t == MAXS - 1) break;
        }
        t++;

        // ---- Step t >= 1: h_t = tanh(z + W_hh @ h_{t-1})  (W_hh from L2) ----
        // sv overwrite is safe: all threads passed grid_barrier's syncthreads
        // and the decision above touches no shared memory.
        {
            const float4* hold = (const float4*)g_h[(t - 1) & 1];
            float4* sv4 = (float4*)sv;
            for (int i = tid; i < HD / 4; i += NTHR) sv4[i] = __ldcg(&hold[i]);
        }
        __syncthreads();

        if (has_row) {
            const float4* row = (const float4*)(W_hh + (size_t)r * HD);
            const float4* hv4 = (const float4*)sv;
            float ah = 0.f;
#pragma unroll 8
            for (int i = lane; i < HD / 4; i += 32) {
                float4 w  = row[i];
                float4 h4 = hv4[i];
                ah = fmaf(w.x, h4.x, ah);
                ah = fmaf(w.y, h4.y, ah);
                ah = fmaf(w.z, h4.z, ah);
                ah = fmaf(w.w, h4.w, ah);
            }
            ah = warp_red(ah);
            if (lane == 0) {
                float hn = tanhf(z_reg + ah);
                __stcg(&g_h[t & 1][r], hn);
                red[warp] = whalt_reg * hn;
            }
        } else if (lane == 0) {
            red[warp] = 0.f;
        }

        // ---- Prefetch this block's W_out rows into L2 (DRAM otherwise idle) ----
        {
            const char* base = (const char*)(W_out + (size_t)r0 * HD);
            const size_t span = (size_t)nrows * HD * sizeof(float);
            for (size_t off = (size_t)tid * 128; off < span; off += (size_t)NTHR * 128)
                pf_l2(base + off);
        }

        __syncthreads();
        if (tid == 0) {
            float p = 0.f;
            for (int w = 0; w < nrows; w++) p += red[w];
            __stcg(&g_part[t][b], p);
        }
        grid_barrier();
    }

    // ---- Final: output = W_out @ h[t] + b_out ; s_new = h[t] ; ponder = t ----
    __syncthreads();
    const float* hf = g_h[t & 1];
    {
        const float4* hf4 = (const float4*)hf;
        float4* sv4 = (float4*)sv;
        for (int i = tid; i < HD / 4; i += NTHR) sv4[i] = __ldcg(&hf4[i]);
    }
    __syncthreads();

    if (has_row) {
        const float4* row = (const float4*)(W_out + (size_t)r * HD);
        const float4* hv4 = (const float4*)sv;
        float acc = 0.f;
#pragma unroll 8
        for (int i = lane; i < HD / 4; i += 32) {
            float4 w  = __ldcs(row + i);   // read-once; hits L2 via prefetch
            float4 h4 = hv4[i];
            acc = fmaf(w.x, h4.x, acc);
            acc = fmaf(w.y, h4.y, acc);
            acc = fmaf(w.z, h4.z, acc);
            acc = fmaf(w.w, h4.w, acc);
        }
        acc = warp_red(acc);
        if (lane == 0) out[r] = acc + b_out[r];
    }
    if (b == 0) {
        for (int i = tid; i < HD; i += NTHR) out[HD + i] = sv[i];
        if (tid == 0) out[2 * HD] = (float)t;
    }
}

extern "C" void kernel_launch(void* const* d_in, const int* in_sizes, int n_in,
                              void* d_out, int out_size) {
    (void)in_sizes; (void)n_in; (void)out_size;
    arnn_kernel<<<NBLK, NTHR>>>(
        (const float*)d_in[0],  // x
        (const float*)d_in[1],  // s
        (const float*)d_in[2],  // W_ih
        (const float*)d_in[3],  // b_ih
        (const float*)d_in[4],  // W_hh
        (const float*)d_in[5],  // b_hh
        (const float*)d_in[6],  // w_halt
        (const float*)d_in[7],  // b_halt
        (const float*)d_in[8],  // W_out
        (const float*)d_in[9],  // b_out
        (float*)d_out);
}

// round 16
// speedup vs baseline: 1.1354x; 1.1354x over previous
#include <cuda_runtime.h>
#include <math.h>

#define HD    4096
#define NBLK  148
#define NTHR  1024
#define NWARP (NTHR / 32)
#define MAXS  16

// Persistent-kernel state (allocation-free scratch).
__device__ float g_h[2][HD];             // double-buffered hidden state
__device__ float g_part[MAXS][NBLK];     // per-step per-block halt partial sums
__device__ unsigned g_barcnt;            // grid barrier arrival count
__device__ volatile unsigned g_bargen;   // grid barrier generation

__device__ __forceinline__ void grid_barrier() {
    __syncthreads();
    if (threadIdx.x == 0) {
        __threadfence();                       // release
        unsigned gen = g_bargen;
        if (atomicAdd(&g_barcnt, 1u) == NBLK - 1u) {
            g_barcnt = 0u;
            __threadfence();
            g_bargen = gen + 1u;
        } else {
            while (g_bargen == gen) { __nanosleep(8); }
        }
        __threadfence();                       // acquire
    }
    __syncthreads();
}

__device__ __forceinline__ float warp_red(float v) {
#pragma unroll
    for (int o = 16; o; o >>= 1) v += __shfl_xor_sync(0xffffffffu, v, o);
    return v;   // full sum on all lanes
}

__device__ __forceinline__ void pf_l2(const void* p) {
    asm volatile("prefetch.global.L2 [%0];" :: "l"(p));
}

__global__ void __launch_bounds__(NTHR, 1) arnn_kernel(
    const float* __restrict__ x,     const float* __restrict__ s,
    const float* __restrict__ W_ih,  const float* __restrict__ b_ih,
    const float* __restrict__ W_hh,  const float* __restrict__ b_hh,
    const float* __restrict__ w_halt,const float* __restrict__ b_halt,
    const float* __restrict__ W_out, const float* __restrict__ b_out,
    float* __restrict__ out)
{
    __shared__ float sx[HD];          // staged x (16 KB)
    __shared__ float sv[HD];          // staged h / s  (16 KB)
    __shared__ float red[NWARP];      // per-warp halt contributions
    __shared__ float bc;              // halt-sum broadcast

    const int tid  = threadIdx.x;
    const int lane = tid & 31;
    const int warp = tid >> 5;
    const int b    = blockIdx.x;

    // Balanced contiguous row ranges: every block gets 27-28 rows.
    const int r0    = (HD * b) / NBLK;
    const int r1    = (HD * (b + 1)) / NBLK;
    const int nrows = r1 - r0;
    const bool has_row = (warp < nrows);
    const int r     = r0 + warp;

    // ---- Stage x and s once (vectorized) ----
    {
        const float4* x4 = (const float4*)x;
        const float4* s4 = (const float4*)s;
        float4* sx4 = (float4*)sx;
        float4* sv4 = (float4*)sv;
        for (int i = tid; i < HD / 4; i += NTHR) { sx4[i] = x4[i]; sv4[i] = s4[i]; }
    }
    __syncthreads();

    const float bhalt = b_halt[0];
    float z_reg = 0.f, whalt_reg = 0.f;

    // ---- Fused phase-0 + step-0, dual-stream interleaved:
    //      z  = W_ih[:,1:] @ x + b_ih + b_hh   (evict-first stream)
    //      a0 = W_hh @ s                        (default: stays in L2 for step 1)
    //      h0 = tanh(z + W_ih[:,0] + a0)
    if (has_row) {
        const float* rowp = W_ih + (size_t)r * (HD + 1) + 1;   // misaligned by (r+1)&3
        const int mis  = (int)(((size_t)rowp >> 2) & 3);
        const int lead = (4 - mis) & 3;
        const float4* vA   = (const float4*)(rowp + lead);
        const float4* rowB = (const float4*)(W_hh + (size_t)r * HD);
        const float4* sv4  = (const float4*)sv;
        const int nA = (HD - lead) >> 2;                        // 1023 or 1024

        float accA = 0.f, accB = 0.f;
        if (lane < lead) accA = fmaf(__ldcs(rowp + lane), sx[lane], accA);

        // Branch-free main body: 992 vectors of each stream (31 iters/lane).
#pragma unroll 4
        for (int i = lane; i < 992; i += 32) {
            float4 wb = rowB[i];
            float4 h4 = sv4[i];
            accB = fmaf(wb.x, h4.x, accB);
            accB = fmaf(wb.y, h4.y, accB);
            accB = fmaf(wb.z, h4.z, accB);
            accB = fmaf(wb.w, h4.w, accB);
            float4 wa = __ldcs(vA + i);
            const int j = lead + 4 * i;
            accA = fmaf(wa.x, sx[j + 0], accA);
            accA = fmaf(wa.y, sx[j + 1], accA);
            accA = fmaf(wa.z, sx[j + 2], accA);
            accA = fmaf(wa.w, sx[j + 3], accA);
        }
        // Tail: B has 1024 vectors, A has 1023 (lead>0) or 1024 (lead==0).
        {
            const int i = 992 + lane;   // 992..1023
            float4 wb = rowB[i];
            float4 h4 = sv4[i];
            accB = fmaf(wb.x, h4.x, accB);
            accB = fmaf(wb.y, h4.y, accB);
            accB = fmaf(wb.z, h4.z, accB);
            accB = fmaf(wb.w, h4.w, accB);
            if (i < nA) {
                float4 wa = __ldcs(vA + i);
                const int j = lead + 4 * i;
                accA = fmaf(wa.x, sx[j + 0], accA);
                accA = fmaf(wa.y, sx[j + 1], accA);
                accA = fmaf(wa.z, sx[j + 2], accA);
                accA = fmaf(wa.w, sx[j + 3], accA);
            }
        }
        const int ts = lead + 4 * nA;
        if (lane < HD - ts) accA = fmaf(__ldcs(rowp + ts + lane), sx[ts + lane], accA);

        accA = warp_red(accA);
        accB = warp_red(accB);
        z_reg     = accA + b_ih[r] + b_hh[r];
        whalt_reg = w_halt[r];
        if (lane == 0) {
            float hn = tanhf(z_reg + __ldcs(rowp - 1) + accB);
            __stcg(&g_h[0][r], hn);
            red[warp] = whalt_reg * hn;
        }
    } else if (lane == 0) {
        red[warp] = 0.f;
    }
    __syncthreads();
    if (tid == 0) {                     // fixed-order per-block partial
        float p = 0.f;
        for (int w = 0; w < nrows; w++) p += red[w];
        __stcg(&g_part[0][b], p);
    }
    grid_barrier();

    float cum = 0.f;
    int   t   = 0;

    for (;;) {
        // ---- Deterministic replicated halt decision ----
        if (warp == 0) {
            float a = 0.f;
#pragma unroll
            for (int i = lane; i < NBLK; i += 32) a += __ldcg(&g_part[t][i]);
            a = warp_red(a);
            if (lane == 0) bc = a;
        }
        __syncthreads();
        {
            float p = 1.f / (1.f + expf(-(bc + bhalt)));
            cum += p;
            if (cum >= 0.99f || t == MAXS - 1) break;
        }
        t++;

        // ---- Step t >= 1: h_t = tanh(z + W_hh @ h_{t-1})  (W_hh from L2) ----
        __syncthreads();
        {
            const float4* hold = (const float4*)g_h[(t - 1) & 1];
            float4* sv4 = (float4*)sv;
            for (int i = tid; i < HD / 4; i += NTHR) sv4[i] = __ldcg(&hold[i]);
        }
        __syncthreads();

        if (has_row) {
            const float4* row = (const float4*)(W_hh + (size_t)r * HD);
            const float4* hv4 = (const float4*)sv;
            float ah = 0.f;
#pragma unroll 8
            for (int i = lane; i < HD / 4; i += 32) {
                float4 w  = row[i];
                float4 h4 = hv4[i];
                ah = fmaf(w.x, h4.x, ah);
                ah = fmaf(w.y, h4.y, ah);
                ah = fmaf(w.z, h4.z, ah);
                ah = fmaf(w.w, h4.w, ah);
            }
            ah = warp_red(ah);
            if (lane == 0) {
                float hn = tanhf(z_reg + ah);
                __stcg(&g_h[t & 1][r], hn);
                red[warp] = whalt_reg * hn;
            }
        } else if (lane == 0) {
            red[warp] = 0.f;
        }

        // ---- Prefetch this block's W_out rows into L2 (DRAM otherwise idle) ----
        {
            const char* base = (const char*)(W_out + (size_t)r0 * HD);
            const size_t span = (size_t)nrows * HD * sizeof(float);
            for (size_t off = (size_t)tid * 128; off < span; off += (size_t)NTHR * 128)
                pf_l2(base + off);
        }

        __syncthreads();
        if (tid == 0) {
            float p = 0.f;
            for (int w = 0; w < nrows; w++) p += red[w];
            __stcg(&g_part[t][b], p);
        }
        grid_barrier();
    }

    // ---- Final: output = W_out @ h[t] + b_out ; s_new = h[t] ; ponder = t ----
    __syncthreads();
    const float* hf = g_h[t & 1];
    {
        const float4* hf4 = (const float4*)hf;
        float4* sv4 = (float4*)sv;
        for (int i = tid; i < HD / 4; i += NTHR) sv4[i] = __ldcg(&hf4[i]);
    }
    __syncthreads();

    if (has_row) {
        const float4* row = (const float4*)(W_out + (size_t)r * HD);
        const float4* hv4 = (const float4*)sv;
        float acc = 0.f;
#pragma unroll 8
        for (int i = lane; i < HD / 4; i += 32) {
            float4 w  = __ldcs(row + i);   // read-once; hits L2 via prefetch
            float4 h4 = hv4[i];
            acc = fmaf(w.x, h4.x, acc);
            acc = fmaf(w.y, h4.y, acc);
            acc = fmaf(w.z, h4.z, acc);
            acc = fmaf(w.w, h4.w, acc);
        }
        acc = warp_red(acc);
        if (lane == 0) out[r] = acc + b_out[r];
    }
    if (b == 0) {
        for (int i = tid; i < HD; i += NTHR) out[HD + i] = sv[i];
        if (tid == 0) out[2 * HD] = (float)t;
    }
}

extern "C" void kernel_launch(void* const* d_in, const int* in_sizes, int n_in,
                              void* d_out, int out_size) {
    (void)in_sizes; (void)n_in; (void)out_size;
    arnn_kernel<<<NBLK, NTHR>>>(
        (const float*)d_in[0],  // x
        (const float*)d_in[1],  // s
        (const float*)d_in[2],  // W_ih
        (const float*)d_in[3],  // b_ih
        (const float*)d_in[4],  // W_hh
        (const float*)d_in[5],  // b_hh
        (const float*)d_in[6],  // w_halt
        (const float*)d_in[7],  // b_halt
        (const float*)d_in[8],  // W_out
        (const float*)d_in[9],  // b_out
        (float*)d_out);
}